// round 3
// baseline (speedup 1.0000x reference)
#include <cuda_runtime.h>
#include <cuda_bf16.h>
#include <math.h>

// Problem constants
#define BB 2
#define SS 2048
#define DD 2048
#define NH 32
#define NKV 8
#define HD 64
#define GG (NH / NKV)   // 4

// ---------------- scratch (static __device__, no allocations) ----------------
__device__ float g_q[BB * SS * NH * HD];     // [b*S+s][h][d]
__device__ float g_k[BB * SS * NKV * HD];
__device__ float g_v[BB * SS * NKV * HD];
__device__ float g_attn[BB * SS * NH * HD];  // attention output, [b,s,h,d]

// ---------------- SGEMM: C[M,N] = A[M,K] @ B[K,N], all row-major -------------
// 128x128 block tile, BK=8, 256 threads, 8x8 per-thread micro-tile.
#define BM 128
#define BN 128
#define BK 8
#define TM 8
#define TN 8

__global__ __launch_bounds__(256)
void sgemm_kernel(int M, int N, int K,
                  const float* __restrict__ A,
                  const float* __restrict__ B,
                  float* __restrict__ C)
{
    __shared__ float As[BK][BM];
    __shared__ float Bs[BK][BN];

    const int tid  = threadIdx.x;
    const int cRow = blockIdx.y;
    const int cCol = blockIdx.x;

    const int tRow = (tid / (BN / TN)) * TM;   // 0..120
    const int tCol = (tid % (BN / TN)) * TN;   // 0..120

    // global load indices
    const int aRow = tid / (BK / 4);           // 0..127
    const int aCol = (tid % (BK / 4)) * 4;     // 0 or 4
    const int bRow = tid / (BN / 4);           // 0..7
    const int bCol = (tid % (BN / 4)) * 4;     // 0..124

    A += (size_t)cRow * BM * K;
    B += (size_t)cCol * BN;
    C += (size_t)cRow * BM * N + (size_t)cCol * BN;

    float acc[TM][TN];
#pragma unroll
    for (int i = 0; i < TM; i++)
#pragma unroll
        for (int j = 0; j < TN; j++) acc[i][j] = 0.0f;

    for (int k0 = 0; k0 < K; k0 += BK) {
        float4 a4 = *(const float4*)(A + (size_t)aRow * K + aCol);
        As[aCol + 0][aRow] = a4.x;
        As[aCol + 1][aRow] = a4.y;
        As[aCol + 2][aRow] = a4.z;
        As[aCol + 3][aRow] = a4.w;
        *(float4*)(&Bs[bRow][bCol]) = *(const float4*)(B + (size_t)bRow * N + bCol);
        __syncthreads();

        A += BK;
        B += (size_t)BK * N;

#pragma unroll
        for (int k = 0; k < BK; k++) {
            float regM[TM], regN[TN];
            *(float4*)(&regM[0]) = *(const float4*)(&As[k][tRow]);
            *(float4*)(&regM[4]) = *(const float4*)(&As[k][tRow + 4]);
            *(float4*)(&regN[0]) = *(const float4*)(&Bs[k][tCol]);
            *(float4*)(&regN[4]) = *(const float4*)(&Bs[k][tCol + 4]);
#pragma unroll
            for (int i = 0; i < TM; i++)
#pragma unroll
                for (int j = 0; j < TN; j++)
                    acc[i][j] = fmaf(regM[i], regN[j], acc[i][j]);
        }
        __syncthreads();
    }

#pragma unroll
    for (int i = 0; i < TM; i++) {
#pragma unroll
        for (int j = 0; j < TN; j += 4) {
            float4 o;
            o.x = acc[i][j + 0];
            o.y = acc[i][j + 1];
            o.z = acc[i][j + 2];
            o.w = acc[i][j + 3];
            *(float4*)(&C[(size_t)(tRow + i) * N + tCol + j]) = o;
        }
    }
}

// ---------------- RoPE (in-place on q and k) ---------------------------------
// Each thread handles one (row, head-slot, freq-index) pair: elements fi and fi+32.
// Angle: ang = s * 10000^(-fi/32), computed as fp32 product (matches reference's
// fp32 outer(t, inv_freq)), then cos/sin of accurately mod-2pi-reduced angle.
__global__ void rope_kernel(float* __restrict__ q, float* __restrict__ k, int total)
{
    int idx = blockIdx.x * blockDim.x + threadIdx.x;
    if (idx >= total) return;

    const int PER_ROW = (NH + NKV) * (HD / 2);   // 40 * 32
    int row  = idx / PER_ROW;
    int rem  = idx % PER_ROW;
    int slot = rem / (HD / 2);
    int fi   = rem % (HD / 2);
    int spos = row % SS;

    // inv_freq in double for the pow, rounded to fp32 (reference uses fp32 pow;
    // ~1ulp agreement)
    float invf = (float)exp2(-(double)fi * 0.41524101186092028); // log2(1e4)/32
    float ang  = (float)spos * invf;

    // 2-term reduction mod 2*pi
    float n = rintf(ang * 0.15915494309189535f);
    float r = fmaf(n, -6.28318548202514648f, ang);
    r       = fmaf(n,  1.74845553e-7f, r);
    float c  = __cosf(r);
    float sn = __sinf(r);

    float* base;
    if (slot < NH) base = q + ((size_t)row * NH + slot) * HD;
    else           base = k + ((size_t)row * NKV + (slot - NH)) * HD;

    float x1 = base[fi];
    float x2 = base[fi + HD / 2];
    base[fi]          = x1 * c - x2 * sn;
    base[fi + HD / 2] = x2 * c + x1 * sn;
}

// ---------------- Flash attention (fp32, causal, GQA) ------------------------
// grid: (S/128, NH, BB); block: 128 threads; each thread owns ONE q row.
// K/V tiles of 64 rows staged in smem; online softmax in chunks of 16 scores.
#define BKV 64
#define CH  16

__global__ __launch_bounds__(128)
void flash_kernel(const float* __restrict__ Q,
                  const float* __restrict__ Kg,
                  const float* __restrict__ Vg,
                  float* __restrict__ O)
{
    const int tid = threadIdx.x;
    const int qt  = blockIdx.x;
    const int h   = blockIdx.y;
    const int b   = blockIdx.z;
    const int row = qt * 128 + tid;
    const int kvh = h / GG;

    __shared__ float Ks[BKV][HD];
    __shared__ float Vs[BKV][HD];

    // load q row (pre-scaled by 1/sqrt(HD))
    float q[HD];
    {
        const float* qp = Q + (((size_t)(b * SS + row)) * NH + h) * HD;
#pragma unroll
        for (int d = 0; d < HD; d += 4) {
            float4 t = *(const float4*)(qp + d);
            q[d + 0] = t.x * 0.125f;
            q[d + 1] = t.y * 0.125f;
            q[d + 2] = t.z * 0.125f;
            q[d + 3] = t.w * 0.125f;
        }
    }

    float o[HD];
#pragma unroll
    for (int d = 0; d < HD; d++) o[d] = 0.0f;
    float m = -1e30f, l = 0.0f;

    const int ntiles = 2 * qt + 2;   // covers k rows 0 .. qt*128+127
    const int lr = tid / 2;          // smem load row
    const int lc = (tid % 2) * 32;   // smem load col offset

    for (int kt = 0; kt < ntiles; kt++) {
        const int kbase = kt * BKV;
        // cooperative K/V tile load
        {
            const float* kp = Kg + (((size_t)(b * SS + kbase + lr)) * NKV + kvh) * HD + lc;
            const float* vp = Vg + (((size_t)(b * SS + kbase + lr)) * NKV + kvh) * HD + lc;
#pragma unroll
            for (int d = 0; d < 32; d += 4) {
                *(float4*)(&Ks[lr][lc + d]) = *(const float4*)(kp + d);
                *(float4*)(&Vs[lr][lc + d]) = *(const float4*)(vp + d);
            }
        }
        __syncthreads();

        const bool full = (kbase + BKV - 1 <= row);

#pragma unroll 1
        for (int jc = 0; jc < BKV; jc += CH) {
            float s[CH];
#pragma unroll
            for (int jj = 0; jj < CH; jj++) {
                float a0 = 0.f, a1 = 0.f, a2 = 0.f, a3 = 0.f;
#pragma unroll
                for (int d = 0; d < HD; d += 16) {
                    float4 k0 = *(const float4*)(&Ks[jc + jj][d + 0]);
                    float4 k1 = *(const float4*)(&Ks[jc + jj][d + 4]);
                    float4 k2 = *(const float4*)(&Ks[jc + jj][d + 8]);
                    float4 k3 = *(const float4*)(&Ks[jc + jj][d + 12]);
                    a0 = fmaf(q[d + 0], k0.x, a0);  a0 = fmaf(q[d + 1], k0.y, a0);
                    a0 = fmaf(q[d + 2], k0.z, a0);  a0 = fmaf(q[d + 3], k0.w, a0);
                    a1 = fmaf(q[d + 4], k1.x, a1);  a1 = fmaf(q[d + 5], k1.y, a1);
                    a1 = fmaf(q[d + 6], k1.z, a1);  a1 = fmaf(q[d + 7], k1.w, a1);
                    a2 = fmaf(q[d + 8], k2.x, a2);  a2 = fmaf(q[d + 9], k2.y, a2);
                    a2 = fmaf(q[d +10], k2.z, a2);  a2 = fmaf(q[d +11], k2.w, a2);
                    a3 = fmaf(q[d +12], k3.x, a3);  a3 = fmaf(q[d +13], k3.y, a3);
                    a3 = fmaf(q[d +14], k3.z, a3);  a3 = fmaf(q[d +15], k3.w, a3);
                }
                s[jj] = (a0 + a1) + (a2 + a3);
            }

            if (!full) {
#pragma unroll
                for (int jj = 0; jj < CH; jj++)
                    if (kbase + jc + jj > row) s[jj] = -1e30f;
            }

            float tmax = s[0];
#pragma unroll
            for (int jj = 1; jj < CH; jj++) tmax = fmaxf(tmax, s[jj]);
            float mnew = fmaxf(m, tmax);
            float corr = __expf(m - mnew);
            l *= corr;
#pragma unroll
            for (int d = 0; d < HD; d++) o[d] *= corr;

#pragma unroll
            for (int jj = 0; jj < CH; jj++) {
                float p = __expf(s[jj] - mnew);
                l += p;
#pragma unroll
                for (int d = 0; d < HD; d += 4) {
                    float4 v4 = *(const float4*)(&Vs[jc + jj][d]);
                    o[d + 0] = fmaf(p, v4.x, o[d + 0]);
                    o[d + 1] = fmaf(p, v4.y, o[d + 1]);
                    o[d + 2] = fmaf(p, v4.z, o[d + 2]);
                    o[d + 3] = fmaf(p, v4.w, o[d + 3]);
                }
            }
            m = mnew;
        }
        __syncthreads();
    }

    const float inv = 1.0f / l;
    float* op = O + (((size_t)(b * SS + row)) * NH + h) * HD;
#pragma unroll
    for (int d = 0; d < HD; d += 4) {
        float4 t;
        t.x = o[d + 0] * inv;
        t.y = o[d + 1] * inv;
        t.z = o[d + 2] * inv;
        t.w = o[d + 3] * inv;
        *(float4*)(op + d) = t;
    }
}

// ---------------- launch -----------------------------------------------------
extern "C" void kernel_launch(void* const* d_in, const int* in_sizes, int n_in,
                              void* d_out, int out_size)
{
    (void)in_sizes; (void)n_in; (void)out_size;
    const float* X  = (const float*)d_in[0];
    const float* Wq = (const float*)d_in[1];
    const float* Wk = (const float*)d_in[2];
    const float* Wv = (const float*)d_in[3];
    const float* Wo = (const float*)d_in[4];

    float *q, *k, *v, *attn;
    cudaGetSymbolAddress((void**)&q,    g_q);
    cudaGetSymbolAddress((void**)&k,    g_k);
    cudaGetSymbolAddress((void**)&v,    g_v);
    cudaGetSymbolAddress((void**)&attn, g_attn);

    const int M = BB * SS;        // 4096
    // QKV projections
    sgemm_kernel<<<dim3((NH * HD) / BN,  M / BM), 256>>>(M, NH * HD,  DD, X, Wq, q);
    sgemm_kernel<<<dim3((NKV * HD) / BN, M / BM), 256>>>(M, NKV * HD, DD, X, Wk, k);
    sgemm_kernel<<<dim3((NKV * HD) / BN, M / BM), 256>>>(M, NKV * HD, DD, X, Wv, v);

    // RoPE on q and k
    int nrope = M * (NH + NKV) * (HD / 2);
    rope_kernel<<<(nrope + 255) / 256, 256>>>(q, k, nrope);

    // causal GQA flash attention
    flash_kernel<<<dim3(SS / 128, NH, BB), 128>>>(q, k, v, attn);

    // output projection -> d_out
    sgemm_kernel<<<dim3(DD / BN, M / BM), 256>>>(M, DD, DD, attn, Wo, (float*)d_out);
}

// round 6
// speedup vs baseline: 1.0336x; 1.0336x over previous
#include <cuda_runtime.h>
#include <cuda_bf16.h>
#include <math.h>
#include <stdint.h>

// Problem constants
#define BB 2
#define SS 2048
#define DD 2048
#define NH 32
#define NKV 8
#define HD 64
#define GG (NH / NKV)   // 4
#define KX (3 * DD)     // expanded K = 6144

// ---------------- scratch (static __device__, no allocations) ----------------
__device__ float g_q[BB * SS * NH * HD];
__device__ float g_k[BB * SS * NKV * HD];
__device__ float g_v[BB * SS * NKV * HD];
__device__ float g_attn[BB * SS * NH * HD];
__device__ float g_invf[HD / 2];

// split-bf16 expanded operands
__device__ __nv_bfloat16 g_Xx[(size_t)BB * SS * KX];        // [4096][6144]
__device__ __nv_bfloat16 g_attnx[(size_t)BB * SS * KX];     // [4096][6144]
__device__ __nv_bfloat16 g_Wqx[(size_t)KX * NH * HD];       // [6144][2048]
__device__ __nv_bfloat16 g_Wkx[(size_t)KX * NKV * HD];      // [6144][512]
__device__ __nv_bfloat16 g_Wvx[(size_t)KX * NKV * HD];
__device__ __nv_bfloat16 g_Wox[(size_t)KX * DD];            // [6144][2048]

// ---------------- inv_freq table (FP64 done once, not per-thread) ------------
__global__ void invf_kernel()
{
    int i = threadIdx.x;
    if (i < HD / 2)
        g_invf[i] = (float)exp2(-(double)i * 0.41524101186092028); // log2(1e4)/32
}

// ---------------- split-bf16 expansion ---------------------------------------
// A [M,K] fp32 row-major -> Ax [M,3K] bf16: cols (3k,3k+1,3k+2) = (hi, lo, hi)
__global__ void expandA_kernel(const float* __restrict__ A,
                               __nv_bfloat16* __restrict__ Ax, int M, int K)
{
    int idx = blockIdx.x * blockDim.x + threadIdx.x;
    int total = M * (K / 4);
    if (idx >= total) return;
    int m  = idx / (K / 4);
    int k4 = (idx % (K / 4)) * 4;
    float4 x = *(const float4*)(A + (size_t)m * K + k4);
    float v[4] = {x.x, x.y, x.z, x.w};
    __align__(8) __nv_bfloat16 out[12];
#pragma unroll
    for (int j = 0; j < 4; j++) {
        __nv_bfloat16 hi = __float2bfloat16(v[j]);
        __nv_bfloat16 lo = __float2bfloat16(v[j] - __bfloat162float(hi));
        out[3 * j + 0] = hi;
        out[3 * j + 1] = lo;
        out[3 * j + 2] = hi;
    }
    uint2* dst = (uint2*)(Ax + (size_t)m * 3 * K + 3 * k4);
    const uint2* src = (const uint2*)out;
    dst[0] = src[0]; dst[1] = src[1]; dst[2] = src[2];
}

// B [K,N] fp32 row-major -> Bx [3K,N] bf16: rows (3k,3k+1,3k+2) = (hi, hi, lo)
__global__ void expandB_kernel(const float* __restrict__ B,
                               __nv_bfloat16* __restrict__ Bx, int K, int N)
{
    int idx = blockIdx.x * blockDim.x + threadIdx.x;
    int total = K * (N / 4);
    if (idx >= total) return;
    int k  = idx / (N / 4);
    int n4 = (idx % (N / 4)) * 4;
    float4 x = *(const float4*)(B + (size_t)k * N + n4);
    float v[4] = {x.x, x.y, x.z, x.w};
    __align__(8) __nv_bfloat16 hi[4], lo[4];
#pragma unroll
    for (int j = 0; j < 4; j++) {
        hi[j] = __float2bfloat16(v[j]);
        lo[j] = __float2bfloat16(v[j] - __bfloat162float(hi[j]));
    }
    __nv_bfloat16* r0 = Bx + (size_t)(3 * k + 0) * N + n4;
    __nv_bfloat16* r1 = Bx + (size_t)(3 * k + 1) * N + n4;
    __nv_bfloat16* r2 = Bx + (size_t)(3 * k + 2) * N + n4;
    *(uint2*)r0 = *(const uint2*)hi;
    *(uint2*)r1 = *(const uint2*)hi;
    *(uint2*)r2 = *(const uint2*)lo;
}

// ---------------- bf16 tensor-core GEMM --------------------------------------
// C[M,N] fp32 = Ax[M,K] @ Bx[K,N] (bf16 in, fp32 accumulate).
// Block tile 128x128, K-chunk 32, 8 warps (4x2), warp tile 32x64.
#define SA 48   // smem row stride (elems) - keeps 16B alignment, tames conflicts

__global__ __launch_bounds__(256)
void gemm_bf16_kernel(int M, int N, int K,
                      const __nv_bfloat16* __restrict__ A,
                      const __nv_bfloat16* __restrict__ B,
                      float* __restrict__ C)
{
    __shared__ __align__(16) __nv_bfloat16 As[128 * SA];
    __shared__ __align__(16) __nv_bfloat16 Bst[128 * SA];   // transposed: Bst[n][k]

    const int tid  = threadIdx.x;
    const int wid  = tid / 32;
    const int lane = tid % 32;
    const int warpM = wid / 2;   // 0..3
    const int warpN = wid % 2;   // 0..1
    const int g = lane >> 2;     // 0..7
    const int t = lane & 3;      // 0..3
    const int rowBase = warpM * 32;
    const int colBase = warpN * 64;

    const __nv_bfloat16* Ag = A + (size_t)blockIdx.y * 128 * K;
    const __nv_bfloat16* Bg = B + (size_t)blockIdx.x * 128;

    const int arow = tid >> 1, acol = (tid & 1) * 16;
    const int brow = tid >> 3, bcol = (tid & 7) * 16;

    float c[2][8][4];
#pragma unroll
    for (int mi = 0; mi < 2; mi++)
#pragma unroll
        for (int ni = 0; ni < 8; ni++)
#pragma unroll
            for (int r = 0; r < 4; r++) c[mi][ni][r] = 0.0f;

    for (int kc = 0; kc < K; kc += 32) {
        // A tile: 128x32 = 4096 elems, 256 threads -> 16 bf16 per thread (2x uint4)
        {
            const __nv_bfloat16* ap = Ag + (size_t)arow * K + kc + acol;
            uint4 av0 = *(const uint4*)(ap);
            uint4 av1 = *(const uint4*)(ap + 8);
            *(uint4*)(As + arow * SA + acol)     = av0;
            *(uint4*)(As + arow * SA + acol + 8) = av1;
        }

        // B tile: 32x128 -> transposed scatter (16 bf16 per thread)
        {
            const __nv_bfloat16* bp = Bg + (size_t)(kc + brow) * N + bcol;
            __align__(16) __nv_bfloat16 tmp[16];
            *(uint4*)(tmp)     = *(const uint4*)(bp);
            *(uint4*)(tmp + 8) = *(const uint4*)(bp + 8);
#pragma unroll
            for (int j = 0; j < 16; j++)
                Bst[(bcol + j) * SA + brow] = tmp[j];
        }
        __syncthreads();

#pragma unroll
        for (int kk = 0; kk < 32; kk += 16) {
            uint32_t af[2][4], bfr[8][2];
#pragma unroll
            for (int mi = 0; mi < 2; mi++) {
                const __nv_bfloat16* p = As + (rowBase + mi * 16 + g) * SA + kk + 2 * t;
                af[mi][0] = *(const uint32_t*)p;
                af[mi][1] = *(const uint32_t*)(p + 8 * SA);
                af[mi][2] = *(const uint32_t*)(p + 8);
                af[mi][3] = *(const uint32_t*)(p + 8 * SA + 8);
            }
#pragma unroll
            for (int ni = 0; ni < 8; ni++) {
                const __nv_bfloat16* p = Bst + (colBase + ni * 8 + g) * SA + kk + 2 * t;
                bfr[ni][0] = *(const uint32_t*)p;
                bfr[ni][1] = *(const uint32_t*)(p + 8);
            }
#pragma unroll
            for (int mi = 0; mi < 2; mi++)
#pragma unroll
                for (int ni = 0; ni < 8; ni++) {
                    asm volatile(
                        "mma.sync.aligned.m16n8k16.row.col.f32.bf16.bf16.f32 "
                        "{%0,%1,%2,%3}, {%4,%5,%6,%7}, {%8,%9}, {%0,%1,%2,%3};\n"
                        : "+f"(c[mi][ni][0]), "+f"(c[mi][ni][1]),
                          "+f"(c[mi][ni][2]), "+f"(c[mi][ni][3])
                        : "r"(af[mi][0]), "r"(af[mi][1]),
                          "r"(af[mi][2]), "r"(af[mi][3]),
                          "r"(bfr[ni][0]), "r"(bfr[ni][1]));
                }
        }
        __syncthreads();
    }

    float* Cg = C + (size_t)blockIdx.y * 128 * N + (size_t)blockIdx.x * 128;
#pragma unroll
    for (int mi = 0; mi < 2; mi++) {
#pragma unroll
        for (int ni = 0; ni < 8; ni++) {
            int r0  = rowBase + mi * 16 + g;
            int col = colBase + ni * 8 + 2 * t;
            float2 lo = make_float2(c[mi][ni][0], c[mi][ni][1]);
            float2 hi = make_float2(c[mi][ni][2], c[mi][ni][3]);
            *(float2*)(Cg + (size_t)r0 * N + col)       = lo;
            *(float2*)(Cg + (size_t)(r0 + 8) * N + col) = hi;
        }
    }
}

// ---------------- RoPE (in-place on q and k) ---------------------------------
__global__ void rope_kernel(float* __restrict__ q, float* __restrict__ k, int total)
{
    int idx = blockIdx.x * blockDim.x + threadIdx.x;
    if (idx >= total) return;

    const int PER_ROW = (NH + NKV) * (HD / 2);   // 40 * 32
    int row  = idx / PER_ROW;
    int rem  = idx % PER_ROW;
    int slot = rem / (HD / 2);
    int fi   = rem % (HD / 2);
    int spos = row % SS;

    float invf = g_invf[fi];
    float ang  = (float)spos * invf;

    // 2-term reduction mod 2*pi
    float n = rintf(ang * 0.15915494309189535f);
    float r = fmaf(n, -6.28318548202514648f, ang);
    r       = fmaf(n,  1.74845553e-7f, r);
    float c  = __cosf(r);
    float sn = __sinf(r);

    float* base;
    if (slot < NH) base = q + ((size_t)row * NH + slot) * HD;
    else           base = k + ((size_t)row * NKV + (slot - NH)) * HD;

    float x1 = base[fi];
    float x2 = base[fi + HD / 2];
    base[fi]          = x1 * c - x2 * sn;
    base[fi + HD / 2] = x2 * c + x1 * sn;
}

// ---------------- Flash attention (fp32, causal, GQA) ------------------------
#define BKV 64
#define CH  16

__global__ __launch_bounds__(128)
void flash_kernel(const float* __restrict__ Q,
                  const float* __restrict__ Kg,
                  const float* __restrict__ Vg,
                  float* __restrict__ O)
{
    const int tid = threadIdx.x;
    const int qt  = blockIdx.x;
    const int h   = blockIdx.y;
    const int b   = blockIdx.z;
    const int row = qt * 128 + tid;
    const int kvh = h / GG;

    __shared__ float Ks[BKV][HD];
    __shared__ float Vs[BKV][HD];

    float q[HD];
    {
        const float* qp = Q + (((size_t)(b * SS + row)) * NH + h) * HD;
#pragma unroll
        for (int d = 0; d < HD; d += 4) {
            float4 t = *(const float4*)(qp + d);
            q[d + 0] = t.x * 0.125f;
            q[d + 1] = t.y * 0.125f;
            q[d + 2] = t.z * 0.125f;
            q[d + 3] = t.w * 0.125f;
        }
    }

    float o[HD];
#pragma unroll
    for (int d = 0; d < HD; d++) o[d] = 0.0f;
    float m = -1e30f, l = 0.0f;

    const int ntiles = 2 * qt + 2;
    const int lr = tid / 2;
    const int lc = (tid % 2) * 32;

    for (int kt = 0; kt < ntiles; kt++) {
        const int kbase = kt * BKV;
        {
            const float* kp = Kg + (((size_t)(b * SS + kbase + lr)) * NKV + kvh) * HD + lc;
            const float* vp = Vg + (((size_t)(b * SS + kbase + lr)) * NKV + kvh) * HD + lc;
#pragma unroll
            for (int d = 0; d < 32; d += 4) {
                *(float4*)(&Ks[lr][lc + d]) = *(const float4*)(kp + d);
                *(float4*)(&Vs[lr][lc + d]) = *(const float4*)(vp + d);
            }
        }
        __syncthreads();

        const bool full = (kbase + BKV - 1 <= row);

#pragma unroll 1
        for (int jc = 0; jc < BKV; jc += CH) {
            float s[CH];
#pragma unroll
            for (int jj = 0; jj < CH; jj++) {
                float a0 = 0.f, a1 = 0.f, a2 = 0.f, a3 = 0.f;
#pragma unroll
                for (int d = 0; d < HD; d += 16) {
                    float4 k0 = *(const float4*)(&Ks[jc + jj][d + 0]);
                    float4 k1 = *(const float4*)(&Ks[jc + jj][d + 4]);
                    float4 k2 = *(const float4*)(&Ks[jc + jj][d + 8]);
                    float4 k3 = *(const float4*)(&Ks[jc + jj][d + 12]);
                    a0 = fmaf(q[d + 0], k0.x, a0);  a0 = fmaf(q[d + 1], k0.y, a0);
                    a0 = fmaf(q[d + 2], k0.z, a0);  a0 = fmaf(q[d + 3], k0.w, a0);
                    a1 = fmaf(q[d + 4], k1.x, a1);  a1 = fmaf(q[d + 5], k1.y, a1);
                    a1 = fmaf(q[d + 6], k1.z, a1);  a1 = fmaf(q[d + 7], k1.w, a1);
                    a2 = fmaf(q[d + 8], k2.x, a2);  a2 = fmaf(q[d + 9], k2.y, a2);
                    a2 = fmaf(q[d +10], k2.z, a2);  a2 = fmaf(q[d +11], k2.w, a2);
                    a3 = fmaf(q[d +12], k3.x, a3);  a3 = fmaf(q[d +13], k3.y, a3);
                    a3 = fmaf(q[d +14], k3.z, a3);  a3 = fmaf(q[d +15], k3.w, a3);
                }
                s[jj] = (a0 + a1) + (a2 + a3);
            }

            if (!full) {
#pragma unroll
                for (int jj = 0; jj < CH; jj++)
                    if (kbase + jc + jj > row) s[jj] = -1e30f;
            }

            float tmax = s[0];
#pragma unroll
            for (int jj = 1; jj < CH; jj++) tmax = fmaxf(tmax, s[jj]);
            float mnew = fmaxf(m, tmax);
            float corr = __expf(m - mnew);
            l *= corr;
#pragma unroll
            for (int d = 0; d < HD; d++) o[d] *= corr;

#pragma unroll
            for (int jj = 0; jj < CH; jj++) {
                float p = __expf(s[jj] - mnew);
                l += p;
#pragma unroll
                for (int d = 0; d < HD; d += 4) {
                    float4 v4 = *(const float4*)(&Vs[jc + jj][d]);
                    o[d + 0] = fmaf(p, v4.x, o[d + 0]);
                    o[d + 1] = fmaf(p, v4.y, o[d + 1]);
                    o[d + 2] = fmaf(p, v4.z, o[d + 2]);
                    o[d + 3] = fmaf(p, v4.w, o[d + 3]);
                }
            }
            m = mnew;
        }
        __syncthreads();
    }

    const float inv = 1.0f / l;
    float* op = O + (((size_t)(b * SS + row)) * NH + h) * HD;
#pragma unroll
    for (int d = 0; d < HD; d += 4) {
        float4 t;
        t.x = o[d + 0] * inv;
        t.y = o[d + 1] * inv;
        t.z = o[d + 2] * inv;
        t.w = o[d + 3] * inv;
        *(float4*)(op + d) = t;
    }
}

// ---------------- launch -----------------------------------------------------
extern "C" void kernel_launch(void* const* d_in, const int* in_sizes, int n_in,
                              void* d_out, int out_size)
{
    (void)in_sizes; (void)n_in; (void)out_size;
    const float* X  = (const float*)d_in[0];
    const float* Wq = (const float*)d_in[1];
    const float* Wk = (const float*)d_in[2];
    const float* Wv = (const float*)d_in[3];
    const float* Wo = (const float*)d_in[4];

    float *q, *k, *v, *attn;
    __nv_bfloat16 *Xx, *attnx, *Wqx, *Wkx, *Wvx, *Wox;
    cudaGetSymbolAddress((void**)&q,     g_q);
    cudaGetSymbolAddress((void**)&k,     g_k);
    cudaGetSymbolAddress((void**)&v,     g_v);
    cudaGetSymbolAddress((void**)&attn,  g_attn);
    cudaGetSymbolAddress((void**)&Xx,    g_Xx);
    cudaGetSymbolAddress((void**)&attnx, g_attnx);
    cudaGetSymbolAddress((void**)&Wqx,   g_Wqx);
    cudaGetSymbolAddress((void**)&Wkx,   g_Wkx);
    cudaGetSymbolAddress((void**)&Wvx,   g_Wvx);
    cudaGetSymbolAddress((void**)&Wox,   g_Wox);

    const int M = BB * SS;        // 4096

    invf_kernel<<<1, 32>>>();

    // split-bf16 expansion
    expandA_kernel<<<(M * (DD / 4) + 255) / 256, 256>>>(X, Xx, M, DD);
    expandB_kernel<<<(DD * (NH * HD / 4) + 255) / 256, 256>>>(Wq, Wqx, DD, NH * HD);
    expandB_kernel<<<(DD * (NKV * HD / 4) + 255) / 256, 256>>>(Wk, Wkx, DD, NKV * HD);
    expandB_kernel<<<(DD * (NKV * HD / 4) + 255) / 256, 256>>>(Wv, Wvx, DD, NKV * HD);
    expandB_kernel<<<(DD * (DD / 4) + 255) / 256, 256>>>(Wo, Wox, DD, DD);

    // QKV projections on tensor cores
    gemm_bf16_kernel<<<dim3((NH * HD) / 128,  M / 128), 256>>>(M, NH * HD,  KX, Xx, Wqx, q);
    gemm_bf16_kernel<<<dim3((NKV * HD) / 128, M / 128), 256>>>(M, NKV * HD, KX, Xx, Wkx, k);
    gemm_bf16_kernel<<<dim3((NKV * HD) / 128, M / 128), 256>>>(M, NKV * HD, KX, Xx, Wvx, v);

    // RoPE
    int nrope = M * (NH + NKV) * (HD / 2);
    rope_kernel<<<(nrope + 255) / 256, 256>>>(q, k, nrope);

    // causal GQA flash attention (fp32 this round)
    flash_kernel<<<dim3(SS / 128, NH, BB), 128>>>(q, k, v, attn);

    // output projection on tensor cores
    expandA_kernel<<<(M * (DD / 4) + 255) / 256, 256>>>(attn, attnx, M, DD);
    gemm_bf16_kernel<<<dim3(DD / 128, M / 128), 256>>>(M, DD, KX, attnx, Wox, (float*)d_out);
}

// round 8
// speedup vs baseline: 1.5643x; 1.5135x over previous
#include <cuda_runtime.h>
#include <cuda_bf16.h>
#include <math.h>
#include <stdint.h>

// Problem constants
#define BB 2
#define SS 2048
#define DD 2048
#define NH 32
#define NKV 8
#define HD 64
#define GG (NH / NKV)   // 4
#define KX (3 * DD)     // expanded K = 6144

// ---------------- scratch (static __device__, no allocations) ----------------
__device__ float g_q[BB * SS * NH * HD];
__device__ float g_k[BB * SS * NKV * HD];
__device__ float g_v[BB * SS * NKV * HD];
__device__ float g_attn[BB * SS * NH * HD];
__device__ float g_invf[HD / 2];

// split-bf16 expanded operands. A-side: [M][3K] row-major (K-major).
// B-side: TRANSPOSED [N][3K] row-major (K-major).
__device__ __nv_bfloat16 g_Xx[(size_t)BB * SS * KX];
__device__ __nv_bfloat16 g_attnx[(size_t)BB * SS * KX];
__device__ __nv_bfloat16 g_Wqx[(size_t)(NH * HD) * KX];
__device__ __nv_bfloat16 g_Wkx[(size_t)(NKV * HD) * KX];
__device__ __nv_bfloat16 g_Wvx[(size_t)(NKV * HD) * KX];
__device__ __nv_bfloat16 g_Wox[(size_t)DD * KX];

// ---------------- inv_freq table ---------------------------------------------
__global__ void invf_kernel()
{
    int i = threadIdx.x;
    if (i < HD / 2)
        g_invf[i] = (float)exp2(-(double)i * 0.41524101186092028); // log2(1e4)/32
}

// ---------------- split-bf16 expansion ---------------------------------------
// A [M,K] fp32 -> Ax [M,3K] bf16: cols (3k,3k+1,3k+2) = (hi, lo, hi)
__global__ void expandA_kernel(const float* __restrict__ A,
                               __nv_bfloat16* __restrict__ Ax, int M, int K)
{
    int idx = blockIdx.x * blockDim.x + threadIdx.x;
    int total = M * (K / 4);
    if (idx >= total) return;
    int m  = idx / (K / 4);
    int k4 = (idx % (K / 4)) * 4;
    float4 x = *(const float4*)(A + (size_t)m * K + k4);
    float v[4] = {x.x, x.y, x.z, x.w};
    __align__(8) __nv_bfloat16 out[12];
#pragma unroll
    for (int j = 0; j < 4; j++) {
        __nv_bfloat16 hi = __float2bfloat16(v[j]);
        __nv_bfloat16 lo = __float2bfloat16(v[j] - __bfloat162float(hi));
        out[3 * j + 0] = hi;
        out[3 * j + 1] = lo;
        out[3 * j + 2] = hi;
    }
    uint2* dst = (uint2*)(Ax + (size_t)m * 3 * K + 3 * k4);
    const uint2* src = (const uint2*)out;
    dst[0] = src[0]; dst[1] = src[1]; dst[2] = src[2];
}

// B [K,N] fp32 -> Bt [N,3K] bf16 (transposed, K-major):
// Bt[n][3k,3k+1,3k+2] = (hi, hi, lo) of B[k][n].
__global__ void expandBt_kernel(const float* __restrict__ B,
                                __nv_bfloat16* __restrict__ Bt, int K, int N)
{
    int idx = blockIdx.x * blockDim.x + threadIdx.x;
    int total = N * (K / 4);
    if (idx >= total) return;
    int n  = idx % N;                 // consecutive lanes -> consecutive n (coalesced reads)
    int k4 = (idx / N) * 4;
    float v[4];
#pragma unroll
    for (int i = 0; i < 4; i++) v[i] = B[(size_t)(k4 + i) * N + n];
    __align__(8) __nv_bfloat16 out[12];
#pragma unroll
    for (int i = 0; i < 4; i++) {
        __nv_bfloat16 hi = __float2bfloat16(v[i]);
        __nv_bfloat16 lo = __float2bfloat16(v[i] - __bfloat162float(hi));
        out[3 * i + 0] = hi;
        out[3 * i + 1] = hi;
        out[3 * i + 2] = lo;
    }
    uint2* dst = (uint2*)(Bt + (size_t)n * 3 * K + 3 * k4);
    const uint2* src = (const uint2*)out;
    dst[0] = src[0]; dst[1] = src[1]; dst[2] = src[2];
}

// ---------------- cp.async helpers -------------------------------------------
__device__ __forceinline__ uint32_t smem_u32(const void* p) {
    uint32_t a;
    asm("{ .reg .u64 t; cvta.to.shared.u64 t, %1; cvt.u32.u64 %0, t; }"
        : "=r"(a) : "l"(p));
    return a;
}
#define CP_ASYNC16(dst, src) \
    asm volatile("cp.async.cg.shared.global [%0], [%1], 16;" \
                 :: "r"(dst), "l"(src) : "memory")
#define CP_COMMIT()  asm volatile("cp.async.commit_group;" ::: "memory")
#define CP_WAIT(n)   asm volatile("cp.async.wait_group %0;" :: "n"(n) : "memory")

// ---------------- mma.sync GEMM: C[M,N] = Ax[M,KX] @ Bt[N,KX]^T --------------
// 256 threads (8 warps, 4x2), block tile 128x128, warp tile 32x64,
// K-chunk 32, cp.async double-buffered smem.
// smem row stride 40 elems (80B): 16B-aligned chunks; 80*r mod 128 distinct
// for r=0..7 -> conflict-free stores and fragment loads.
#define GST 40

__global__ __launch_bounds__(256)
void gemm_bf16_kernel(int M, int N, const __nv_bfloat16* __restrict__ A,
                      const __nv_bfloat16* __restrict__ Bt,
                      float* __restrict__ C)
{
    __shared__ __align__(16) __nv_bfloat16 sA[2][128 * GST];
    __shared__ __align__(16) __nv_bfloat16 sB[2][128 * GST];

    const int tid  = threadIdx.x;
    const int wid  = tid / 32;
    const int lane = tid % 32;
    const int warpM = wid / 2;       // 0..3
    const int warpN = wid % 2;       // 0..1
    const int g = lane >> 2;         // 0..7
    const int t = lane & 3;          // 0..3
    const int rowBase = warpM * 32;
    const int colBase = warpN * 64;

    const __nv_bfloat16* Ag = A  + (size_t)blockIdx.y * 128 * KX;
    const __nv_bfloat16* Bg = Bt + (size_t)blockIdx.x * 128 * KX;

    // async-copy mapping: 512 chunks of 16B per tile, 2 per thread
    const int r0 = tid >> 2;          // row for chunk tid (0..63)
    const int c0 = (tid & 3) * 8;     // col elems (0,8,16,24)
    const int r1 = r0 + 64;           // row for chunk tid+256

    const uint32_t sA0 = smem_u32(sA[0]), sA1 = smem_u32(sA[1]);
    const uint32_t sB0 = smem_u32(sB[0]), sB1 = smem_u32(sB[1]);
    const uint32_t dA0 = r0 * GST + c0, dA1 = r1 * GST + c0;

    float c[2][8][4];
#pragma unroll
    for (int mi = 0; mi < 2; mi++)
#pragma unroll
        for (int ni = 0; ni < 8; ni++)
#pragma unroll
            for (int r = 0; r < 4; r++) c[mi][ni][r] = 0.0f;

    const int NCH = KX / 32;   // 192

    // prologue: stage 0
    CP_ASYNC16(sA0 + 2 * dA0, Ag + (size_t)r0 * KX + c0);
    CP_ASYNC16(sA0 + 2 * dA1, Ag + (size_t)r1 * KX + c0);
    CP_ASYNC16(sB0 + 2 * dA0, Bg + (size_t)r0 * KX + c0);
    CP_ASYNC16(sB0 + 2 * dA1, Bg + (size_t)r1 * KX + c0);
    CP_COMMIT();

    for (int ch = 0; ch < NCH; ch++) {
        if (ch + 1 < NCH) {
            const int kc = (ch + 1) * 32;
            const uint32_t a = ((ch + 1) & 1) ? sA1 : sA0;
            const uint32_t b = ((ch + 1) & 1) ? sB1 : sB0;
            CP_ASYNC16(a + 2 * dA0, Ag + (size_t)r0 * KX + kc + c0);
            CP_ASYNC16(a + 2 * dA1, Ag + (size_t)r1 * KX + kc + c0);
            CP_ASYNC16(b + 2 * dA0, Bg + (size_t)r0 * KX + kc + c0);
            CP_ASYNC16(b + 2 * dA1, Bg + (size_t)r1 * KX + kc + c0);
            CP_COMMIT();
            CP_WAIT(1);
        } else {
            CP_WAIT(0);
        }
        __syncthreads();

        const __nv_bfloat16* As = (ch & 1) ? sA[1] : sA[0];
        const __nv_bfloat16* Bs = (ch & 1) ? sB[1] : sB[0];

#pragma unroll
        for (int kk = 0; kk < 32; kk += 16) {
            uint32_t af[2][4], bfr[8][2];
#pragma unroll
            for (int mi = 0; mi < 2; mi++) {
                const __nv_bfloat16* p = As + (rowBase + mi * 16 + g) * GST + kk + 2 * t;
                af[mi][0] = *(const uint32_t*)p;
                af[mi][1] = *(const uint32_t*)(p + 8 * GST);
                af[mi][2] = *(const uint32_t*)(p + 8);
                af[mi][3] = *(const uint32_t*)(p + 8 * GST + 8);
            }
#pragma unroll
            for (int ni = 0; ni < 8; ni++) {
                const __nv_bfloat16* p = Bs + (colBase + ni * 8 + g) * GST + kk + 2 * t;
                bfr[ni][0] = *(const uint32_t*)p;
                bfr[ni][1] = *(const uint32_t*)(p + 8);
            }
#pragma unroll
            for (int mi = 0; mi < 2; mi++)
#pragma unroll
                for (int ni = 0; ni < 8; ni++) {
                    asm volatile(
                        "mma.sync.aligned.m16n8k16.row.col.f32.bf16.bf16.f32 "
                        "{%0,%1,%2,%3}, {%4,%5,%6,%7}, {%8,%9}, {%0,%1,%2,%3};\n"
                        : "+f"(c[mi][ni][0]), "+f"(c[mi][ni][1]),
                          "+f"(c[mi][ni][2]), "+f"(c[mi][ni][3])
                        : "r"(af[mi][0]), "r"(af[mi][1]),
                          "r"(af[mi][2]), "r"(af[mi][3]),
                          "r"(bfr[ni][0]), "r"(bfr[ni][1]));
                }
        }
        __syncthreads();
    }

    float* Cg = C + (size_t)blockIdx.y * 128 * N + (size_t)blockIdx.x * 128;
#pragma unroll
    for (int mi = 0; mi < 2; mi++) {
#pragma unroll
        for (int ni = 0; ni < 8; ni++) {
            int rr  = rowBase + mi * 16 + g;
            int col = colBase + ni * 8 + 2 * t;
            float2 lo = make_float2(c[mi][ni][0], c[mi][ni][1]);
            float2 hi = make_float2(c[mi][ni][2], c[mi][ni][3]);
            *(float2*)(Cg + (size_t)rr * N + col)       = lo;
            *(float2*)(Cg + (size_t)(rr + 8) * N + col) = hi;
        }
    }
}

// ---------------- RoPE (in-place on q and k) ---------------------------------
__global__ void rope_kernel(float* __restrict__ q, float* __restrict__ k, int total)
{
    int idx = blockIdx.x * blockDim.x + threadIdx.x;
    if (idx >= total) return;

    const int PER_ROW = (NH + NKV) * (HD / 2);
    int row  = idx / PER_ROW;
    int rem  = idx % PER_ROW;
    int slot = rem / (HD / 2);
    int fi   = rem % (HD / 2);
    int spos = row % SS;

    float invf = g_invf[fi];
    float ang  = (float)spos * invf;

    float n = rintf(ang * 0.15915494309189535f);
    float r = fmaf(n, -6.28318548202514648f, ang);
    r       = fmaf(n,  1.74845553e-7f, r);
    float c  = __cosf(r);
    float sn = __sinf(r);

    float* base;
    if (slot < NH) base = q + ((size_t)row * NH + slot) * HD;
    else           base = k + ((size_t)row * NKV + (slot - NH)) * HD;

    float x1 = base[fi];
    float x2 = base[fi + HD / 2];
    base[fi]          = x1 * c - x2 * sn;
    base[fi + HD / 2] = x2 * c + x1 * sn;
}

// ---------------- Flash attention (fp32, causal, GQA) ------------------------
#define BKV 64
#define FCH 16

__global__ __launch_bounds__(128)
void flash_kernel(const float* __restrict__ Q,
                  const float* __restrict__ Kg,
                  const float* __restrict__ Vg,
                  float* __restrict__ O)
{
    const int tid = threadIdx.x;
    const int qt  = blockIdx.x;
    const int h   = blockIdx.y;
    const int b   = blockIdx.z;
    const int row = qt * 128 + tid;
    const int kvh = h / GG;

    __shared__ float Ks[BKV][HD];
    __shared__ float Vs[BKV][HD];

    float q[HD];
    {
        const float* qp = Q + (((size_t)(b * SS + row)) * NH + h) * HD;
#pragma unroll
        for (int d = 0; d < HD; d += 4) {
            float4 t = *(const float4*)(qp + d);
            q[d + 0] = t.x * 0.125f;
            q[d + 1] = t.y * 0.125f;
            q[d + 2] = t.z * 0.125f;
            q[d + 3] = t.w * 0.125f;
        }
    }

    float o[HD];
#pragma unroll
    for (int d = 0; d < HD; d++) o[d] = 0.0f;
    float m = -1e30f, l = 0.0f;

    const int ntiles = 2 * qt + 2;
    const int lr = tid / 2;
    const int lc = (tid % 2) * 32;

    for (int kt = 0; kt < ntiles; kt++) {
        const int kbase = kt * BKV;
        {
            const float* kp = Kg + (((size_t)(b * SS + kbase + lr)) * NKV + kvh) * HD + lc;
            const float* vp = Vg + (((size_t)(b * SS + kbase + lr)) * NKV + kvh) * HD + lc;
#pragma unroll
            for (int d = 0; d < 32; d += 4) {
                *(float4*)(&Ks[lr][lc + d]) = *(const float4*)(kp + d);
                *(float4*)(&Vs[lr][lc + d]) = *(const float4*)(vp + d);
            }
        }
        __syncthreads();

        const bool full = (kbase + BKV - 1 <= row);

#pragma unroll 1
        for (int jc = 0; jc < BKV; jc += FCH) {
            float s[FCH];
#pragma unroll
            for (int jj = 0; jj < FCH; jj++) {
                float a0 = 0.f, a1 = 0.f, a2 = 0.f, a3 = 0.f;
#pragma unroll
                for (int d = 0; d < HD; d += 16) {
                    float4 k0 = *(const float4*)(&Ks[jc + jj][d + 0]);
                    float4 k1 = *(const float4*)(&Ks[jc + jj][d + 4]);
                    float4 k2 = *(const float4*)(&Ks[jc + jj][d + 8]);
                    float4 k3 = *(const float4*)(&Ks[jc + jj][d + 12]);
                    a0 = fmaf(q[d + 0], k0.x, a0);  a0 = fmaf(q[d + 1], k0.y, a0);
                    a0 = fmaf(q[d + 2], k0.z, a0);  a0 = fmaf(q[d + 3], k0.w, a0);
                    a1 = fmaf(q[d + 4], k1.x, a1);  a1 = fmaf(q[d + 5], k1.y, a1);
                    a1 = fmaf(q[d + 6], k1.z, a1);  a1 = fmaf(q[d + 7], k1.w, a1);
                    a2 = fmaf(q[d + 8], k2.x, a2);  a2 = fmaf(q[d + 9], k2.y, a2);
                    a2 = fmaf(q[d +10], k2.z, a2);  a2 = fmaf(q[d +11], k2.w, a2);
                    a3 = fmaf(q[d +12], k3.x, a3);  a3 = fmaf(q[d +13], k3.y, a3);
                    a3 = fmaf(q[d +14], k3.z, a3);  a3 = fmaf(q[d +15], k3.w, a3);
                }
                s[jj] = (a0 + a1) + (a2 + a3);
            }

            if (!full) {
#pragma unroll
                for (int jj = 0; jj < FCH; jj++)
                    if (kbase + jc + jj > row) s[jj] = -1e30f;
            }

            float tmax = s[0];
#pragma unroll
            for (int jj = 1; jj < FCH; jj++) tmax = fmaxf(tmax, s[jj]);
            float mnew = fmaxf(m, tmax);
            float corr = __expf(m - mnew);
            l *= corr;
#pragma unroll
            for (int d = 0; d < HD; d++) o[d] *= corr;

#pragma unroll
            for (int jj = 0; jj < FCH; jj++) {
                float p = __expf(s[jj] - mnew);
                l += p;
#pragma unroll
                for (int d = 0; d < HD; d += 4) {
                    float4 v4 = *(const float4*)(&Vs[jc + jj][d]);
                    o[d + 0] = fmaf(p, v4.x, o[d + 0]);
                    o[d + 1] = fmaf(p, v4.y, o[d + 1]);
                    o[d + 2] = fmaf(p, v4.z, o[d + 2]);
                    o[d + 3] = fmaf(p, v4.w, o[d + 3]);
                }
            }
            m = mnew;
        }
        __syncthreads();
    }

    const float inv = 1.0f / l;
    float* op = O + (((size_t)(b * SS + row)) * NH + h) * HD;
#pragma unroll
    for (int d = 0; d < HD; d += 4) {
        float4 t;
        t.x = o[d + 0] * inv;
        t.y = o[d + 1] * inv;
        t.z = o[d + 2] * inv;
        t.w = o[d + 3] * inv;
        *(float4*)(op + d) = t;
    }
}

// ---------------- launch -----------------------------------------------------
extern "C" void kernel_launch(void* const* d_in, const int* in_sizes, int n_in,
                              void* d_out, int out_size)
{
    (void)in_sizes; (void)n_in; (void)out_size;
    const float* X  = (const float*)d_in[0];
    const float* Wq = (const float*)d_in[1];
    const float* Wk = (const float*)d_in[2];
    const float* Wv = (const float*)d_in[3];
    const float* Wo = (const float*)d_in[4];

    float *q, *k, *v, *attn;
    __nv_bfloat16 *Xx, *attnx, *Wqx, *Wkx, *Wvx, *Wox;
    cudaGetSymbolAddress((void**)&q,     g_q);
    cudaGetSymbolAddress((void**)&k,     g_k);
    cudaGetSymbolAddress((void**)&v,     g_v);
    cudaGetSymbolAddress((void**)&attn,  g_attn);
    cudaGetSymbolAddress((void**)&Xx,    g_Xx);
    cudaGetSymbolAddress((void**)&attnx, g_attnx);
    cudaGetSymbolAddress((void**)&Wqx,   g_Wqx);
    cudaGetSymbolAddress((void**)&Wkx,   g_Wkx);
    cudaGetSymbolAddress((void**)&Wvx,   g_Wvx);
    cudaGetSymbolAddress((void**)&Wox,   g_Wox);

    const int M = BB * SS;        // 4096

    invf_kernel<<<1, 32>>>();

    // split-bf16 expansion (A row-major, B transposed K-major)
    expandA_kernel<<<(M * (DD / 4) + 255) / 256, 256>>>(X, Xx, M, DD);
    expandBt_kernel<<<((NH * HD) * (DD / 4) + 255) / 256, 256>>>(Wq, Wqx, DD, NH * HD);
    expandBt_kernel<<<((NKV * HD) * (DD / 4) + 255) / 256, 256>>>(Wk, Wkx, DD, NKV * HD);
    expandBt_kernel<<<((NKV * HD) * (DD / 4) + 255) / 256, 256>>>(Wv, Wvx, DD, NKV * HD);
    expandBt_kernel<<<(DD * (DD / 4) + 255) / 256, 256>>>(Wo, Wox, DD, DD);

    // QKV projections on tensor cores (pipelined mma.sync)
    gemm_bf16_kernel<<<dim3((NH * HD) / 128,  M / 128), 256>>>(M, NH * HD,  Xx, Wqx, q);
    gemm_bf16_kernel<<<dim3((NKV * HD) / 128, M / 128), 256>>>(M, NKV * HD, Xx, Wkx, k);
    gemm_bf16_kernel<<<dim3((NKV * HD) / 128, M / 128), 256>>>(M, NKV * HD, Xx, Wvx, v);

    // RoPE
    int nrope = M * (NH + NKV) * (HD / 2);
    rope_kernel<<<(nrope + 255) / 256, 256>>>(q, k, nrope);

    // causal GQA flash attention (fp32 this round)
    flash_kernel<<<dim3(SS / 128, NH, BB), 128>>>(q, k, v, attn);

    // output projection on tensor cores
    expandA_kernel<<<(M * (DD / 4) + 255) / 256, 256>>>(attn, attnx, M, DD);
    gemm_bf16_kernel<<<dim3(DD / 128, M / 128), 256>>>(M, DD, attnx, Wox, (float*)d_out);
}

// round 9
// speedup vs baseline: 2.4047x; 1.5372x over previous
#include <cuda_runtime.h>
#include <cuda_bf16.h>
#include <math.h>
#include <stdint.h>

// Problem constants
#define BB 2
#define SS 2048
#define DD 2048
#define NH 32
#define NKV 8
#define HD 64
#define GG (NH / NKV)   // 4
#define KX (3 * DD)     // expanded K = 6144

// ---------------- scratch (static __device__, no allocations) ----------------
__device__ float g_q[BB * SS * NH * HD];
__device__ float g_k[BB * SS * NKV * HD];
__device__ float g_v[BB * SS * NKV * HD];
__device__ float g_attn[BB * SS * NH * HD];
__device__ float g_invf[HD / 2];

// split-bf16 expanded operands. A-side: [M][3K] row-major (K-major).
// B-side: TRANSPOSED [N][3K] row-major (K-major).
__device__ __nv_bfloat16 g_Xx[(size_t)BB * SS * KX];
__device__ __nv_bfloat16 g_attnx[(size_t)BB * SS * KX];
__device__ __nv_bfloat16 g_Wqx[(size_t)(NH * HD) * KX];
__device__ __nv_bfloat16 g_Wkx[(size_t)(NKV * HD) * KX];
__device__ __nv_bfloat16 g_Wvx[(size_t)(NKV * HD) * KX];
__device__ __nv_bfloat16 g_Wox[(size_t)DD * KX];

// ---------------- inv_freq table ---------------------------------------------
__global__ void invf_kernel()
{
    int i = threadIdx.x;
    if (i < HD / 2)
        g_invf[i] = (float)exp2(-(double)i * 0.41524101186092028); // log2(1e4)/32
}

// ---------------- split-bf16 expansion ---------------------------------------
__global__ void expandA_kernel(const float* __restrict__ A,
                               __nv_bfloat16* __restrict__ Ax, int M, int K)
{
    int idx = blockIdx.x * blockDim.x + threadIdx.x;
    int total = M * (K / 4);
    if (idx >= total) return;
    int m  = idx / (K / 4);
    int k4 = (idx % (K / 4)) * 4;
    float4 x = *(const float4*)(A + (size_t)m * K + k4);
    float v[4] = {x.x, x.y, x.z, x.w};
    __align__(8) __nv_bfloat16 out[12];
#pragma unroll
    for (int j = 0; j < 4; j++) {
        __nv_bfloat16 hi = __float2bfloat16(v[j]);
        __nv_bfloat16 lo = __float2bfloat16(v[j] - __bfloat162float(hi));
        out[3 * j + 0] = hi;
        out[3 * j + 1] = lo;
        out[3 * j + 2] = hi;
    }
    uint2* dst = (uint2*)(Ax + (size_t)m * 3 * K + 3 * k4);
    const uint2* src = (const uint2*)out;
    dst[0] = src[0]; dst[1] = src[1]; dst[2] = src[2];
}

__global__ void expandBt_kernel(const float* __restrict__ B,
                                __nv_bfloat16* __restrict__ Bt, int K, int N)
{
    int idx = blockIdx.x * blockDim.x + threadIdx.x;
    int total = N * (K / 4);
    if (idx >= total) return;
    int n  = idx % N;
    int k4 = (idx / N) * 4;
    float v[4];
#pragma unroll
    for (int i = 0; i < 4; i++) v[i] = B[(size_t)(k4 + i) * N + n];
    __align__(8) __nv_bfloat16 out[12];
#pragma unroll
    for (int i = 0; i < 4; i++) {
        __nv_bfloat16 hi = __float2bfloat16(v[i]);
        __nv_bfloat16 lo = __float2bfloat16(v[i] - __bfloat162float(hi));
        out[3 * i + 0] = hi;
        out[3 * i + 1] = hi;
        out[3 * i + 2] = lo;
    }
    uint2* dst = (uint2*)(Bt + (size_t)n * 3 * K + 3 * k4);
    const uint2* src = (const uint2*)out;
    dst[0] = src[0]; dst[1] = src[1]; dst[2] = src[2];
}

// ---------------- helpers ----------------------------------------------------
__device__ __forceinline__ uint32_t smem_u32(const void* p) {
    uint32_t a;
    asm("{ .reg .u64 t; cvta.to.shared.u64 t, %1; cvt.u32.u64 %0, t; }"
        : "=r"(a) : "l"(p));
    return a;
}
#define CP_ASYNC16(dst, src) \
    asm volatile("cp.async.cg.shared.global [%0], [%1], 16;" \
                 :: "r"(dst), "l"(src) : "memory")
#define CP_COMMIT()  asm volatile("cp.async.commit_group;" ::: "memory")
#define CP_WAIT(n)   asm volatile("cp.async.wait_group %0;" :: "n"(n) : "memory")

#define MMA16816(C, A, B0, B1) \
    asm volatile("mma.sync.aligned.m16n8k16.row.col.f32.bf16.bf16.f32 " \
                 "{%0,%1,%2,%3}, {%4,%5,%6,%7}, {%8,%9}, {%0,%1,%2,%3};\n" \
                 : "+f"((C)[0]), "+f"((C)[1]), "+f"((C)[2]), "+f"((C)[3]) \
                 : "r"((A)[0]), "r"((A)[1]), "r"((A)[2]), "r"((A)[3]), \
                   "r"(B0), "r"(B1))

__device__ __forceinline__ uint32_t pack_bf16hi(float a, float b) {
    __nv_bfloat162 h;
    h.x = __float2bfloat16_rn(a);
    h.y = __float2bfloat16_rn(b);
    return *(uint32_t*)&h;
}
__device__ __forceinline__ uint32_t pack_bf16lo(float a, float b) {
    __nv_bfloat16 ha = __float2bfloat16_rn(a);
    __nv_bfloat16 hb = __float2bfloat16_rn(b);
    __nv_bfloat162 l;
    l.x = __float2bfloat16_rn(a - __bfloat162float(ha));
    l.y = __float2bfloat16_rn(b - __bfloat162float(hb));
    return *(uint32_t*)&l;
}

// fast e^x on the fma pipe (x <= 0), rel err ~3e-6
__device__ __forceinline__ float expf_fast(float x) {
    float y = x * 1.44269504088896f;
    y = fmaxf(y, -126.0f);
    float n = rintf(y);
    float f = y - n;
    float p = 1.33335581464e-3f;
    p = fmaf(p, f, 9.61812910763e-3f);
    p = fmaf(p, f, 5.55041086648e-2f);
    p = fmaf(p, f, 2.40226506959e-1f);
    p = fmaf(p, f, 6.93147180560e-1f);
    p = fmaf(p, f, 1.0f);
    float sc = __int_as_float(((int)n + 127) << 23);
    return p * sc;
}

// ---------------- mma.sync GEMM (unchanged from R8) --------------------------
#define GST 40

__global__ __launch_bounds__(256)
void gemm_bf16_kernel(int M, int N, const __nv_bfloat16* __restrict__ A,
                      const __nv_bfloat16* __restrict__ Bt,
                      float* __restrict__ C)
{
    __shared__ __align__(16) __nv_bfloat16 sA[2][128 * GST];
    __shared__ __align__(16) __nv_bfloat16 sB[2][128 * GST];

    const int tid  = threadIdx.x;
    const int wid  = tid / 32;
    const int lane = tid % 32;
    const int warpM = wid / 2;
    const int warpN = wid % 2;
    const int g = lane >> 2;
    const int t = lane & 3;
    const int rowBase = warpM * 32;
    const int colBase = warpN * 64;

    const __nv_bfloat16* Ag = A  + (size_t)blockIdx.y * 128 * KX;
    const __nv_bfloat16* Bg = Bt + (size_t)blockIdx.x * 128 * KX;

    const int r0 = tid >> 2;
    const int c0 = (tid & 3) * 8;
    const int r1 = r0 + 64;

    const uint32_t sA0 = smem_u32(sA[0]), sA1 = smem_u32(sA[1]);
    const uint32_t sB0 = smem_u32(sB[0]), sB1 = smem_u32(sB[1]);
    const uint32_t dA0 = r0 * GST + c0, dA1 = r1 * GST + c0;

    float c[2][8][4];
#pragma unroll
    for (int mi = 0; mi < 2; mi++)
#pragma unroll
        for (int ni = 0; ni < 8; ni++)
#pragma unroll
            for (int r = 0; r < 4; r++) c[mi][ni][r] = 0.0f;

    const int NCH = KX / 32;

    CP_ASYNC16(sA0 + 2 * dA0, Ag + (size_t)r0 * KX + c0);
    CP_ASYNC16(sA0 + 2 * dA1, Ag + (size_t)r1 * KX + c0);
    CP_ASYNC16(sB0 + 2 * dA0, Bg + (size_t)r0 * KX + c0);
    CP_ASYNC16(sB0 + 2 * dA1, Bg + (size_t)r1 * KX + c0);
    CP_COMMIT();

    for (int ch = 0; ch < NCH; ch++) {
        if (ch + 1 < NCH) {
            const int kc = (ch + 1) * 32;
            const uint32_t a = ((ch + 1) & 1) ? sA1 : sA0;
            const uint32_t b = ((ch + 1) & 1) ? sB1 : sB0;
            CP_ASYNC16(a + 2 * dA0, Ag + (size_t)r0 * KX + kc + c0);
            CP_ASYNC16(a + 2 * dA1, Ag + (size_t)r1 * KX + kc + c0);
            CP_ASYNC16(b + 2 * dA0, Bg + (size_t)r0 * KX + kc + c0);
            CP_ASYNC16(b + 2 * dA1, Bg + (size_t)r1 * KX + kc + c0);
            CP_COMMIT();
            CP_WAIT(1);
        } else {
            CP_WAIT(0);
        }
        __syncthreads();

        const __nv_bfloat16* As = (ch & 1) ? sA[1] : sA[0];
        const __nv_bfloat16* Bs = (ch & 1) ? sB[1] : sB[0];

#pragma unroll
        for (int kk = 0; kk < 32; kk += 16) {
            uint32_t af[2][4], bfr[8][2];
#pragma unroll
            for (int mi = 0; mi < 2; mi++) {
                const __nv_bfloat16* p = As + (rowBase + mi * 16 + g) * GST + kk + 2 * t;
                af[mi][0] = *(const uint32_t*)p;
                af[mi][1] = *(const uint32_t*)(p + 8 * GST);
                af[mi][2] = *(const uint32_t*)(p + 8);
                af[mi][3] = *(const uint32_t*)(p + 8 * GST + 8);
            }
#pragma unroll
            for (int ni = 0; ni < 8; ni++) {
                const __nv_bfloat16* p = Bs + (colBase + ni * 8 + g) * GST + kk + 2 * t;
                bfr[ni][0] = *(const uint32_t*)p;
                bfr[ni][1] = *(const uint32_t*)(p + 8);
            }
#pragma unroll
            for (int mi = 0; mi < 2; mi++)
#pragma unroll
                for (int ni = 0; ni < 8; ni++)
                    MMA16816(c[mi][ni], af[mi], bfr[ni][0], bfr[ni][1]);
        }
        __syncthreads();
    }

    float* Cg = C + (size_t)blockIdx.y * 128 * N + (size_t)blockIdx.x * 128;
#pragma unroll
    for (int mi = 0; mi < 2; mi++) {
#pragma unroll
        for (int ni = 0; ni < 8; ni++) {
            int rr  = rowBase + mi * 16 + g;
            int col = colBase + ni * 8 + 2 * t;
            float2 lo = make_float2(c[mi][ni][0], c[mi][ni][1]);
            float2 hi = make_float2(c[mi][ni][2], c[mi][ni][3]);
            *(float2*)(Cg + (size_t)rr * N + col)       = lo;
            *(float2*)(Cg + (size_t)(rr + 8) * N + col) = hi;
        }
    }
}

// ---------------- RoPE (unchanged) -------------------------------------------
__global__ void rope_kernel(float* __restrict__ q, float* __restrict__ k, int total)
{
    int idx = blockIdx.x * blockDim.x + threadIdx.x;
    if (idx >= total) return;

    const int PER_ROW = (NH + NKV) * (HD / 2);
    int row  = idx / PER_ROW;
    int rem  = idx % PER_ROW;
    int slot = rem / (HD / 2);
    int fi   = rem % (HD / 2);
    int spos = row % SS;

    float invf = g_invf[fi];
    float ang  = (float)spos * invf;

    float n = rintf(ang * 0.15915494309189535f);
    float r = fmaf(n, -6.28318548202514648f, ang);
    r       = fmaf(n,  1.74845553e-7f, r);
    float c  = __cosf(r);
    float sn = __sinf(r);

    float* base;
    if (slot < NH) base = q + ((size_t)row * NH + slot) * HD;
    else           base = k + ((size_t)row * NKV + (slot - NH)) * HD;

    float x1 = base[fi];
    float x2 = base[fi + HD / 2];
    base[fi]          = x1 * c - x2 * sn;
    base[fi + HD / 2] = x2 * c + x1 * sn;
}

// ---------------- Tensor-core flash attention (split-bf16, causal, GQA) ------
// 128 threads (4 warps x 16 q-rows), KV tile 64.
// K hi/lo smem [key][d]; V hi/lo smem TRANSPOSED [d][key]. Q hi/lo frags in regs.
#define FTS 72   // smem row stride (elems): (g*36 + t) mod 32 distinct -> conflict-free

__global__ __launch_bounds__(128)
void flash_mma_kernel(const float* __restrict__ Q,
                      const float* __restrict__ Kg,
                      const float* __restrict__ Vg,
                      float* __restrict__ O)
{
    __shared__ __align__(16) __nv_bfloat16 sKh[64 * FTS];
    __shared__ __align__(16) __nv_bfloat16 sKl[64 * FTS];
    __shared__ __align__(16) __nv_bfloat16 sVh[64 * FTS];   // [d][key]
    __shared__ __align__(16) __nv_bfloat16 sVl[64 * FTS];

    const int tid = threadIdx.x;
    const int w    = tid >> 5;
    const int lane = tid & 31;
    const int g = lane >> 2, t = lane & 3;
    const int qt = blockIdx.x, h = blockIdx.y, b = blockIdx.z;
    const int rbase = qt * 64 + w * 16;
    const int kvh = h / GG;

    // Q fragments (hi/lo), scaled by 1/sqrt(HD)
    uint32_t qh[4][4], ql[4][4];
#pragma unroll
    for (int kk = 0; kk < 4; kk++) {
#pragma unroll
        for (int pt = 0; pt < 4; pt++) {
            int row = rbase + g + (pt & 1) * 8;
            int col = kk * 16 + 2 * t + (pt >> 1) * 8;
            const float* qp = Q + (((size_t)(b * SS + row)) * NH + h) * HD + col;
            float2 qv = *(const float2*)qp;
            float x0 = qv.x * 0.125f, x1 = qv.y * 0.125f;
            qh[kk][pt] = pack_bf16hi(x0, x1);
            ql[kk][pt] = pack_bf16lo(x0, x1);
        }
    }

    float o[8][4];
#pragma unroll
    for (int ni = 0; ni < 8; ni++)
#pragma unroll
        for (int j = 0; j < 4; j++) o[ni][j] = 0.0f;
    float m0 = -1e30f, m1 = -1e30f, l0 = 0.0f, l1 = 0.0f;

    const int ntiles = qt + 1;
    const int lr  = tid >> 1;          // tile load row 0..63
    const int lcg = (tid & 1) * 32;    // d group

    for (int kt = 0; kt < ntiles; kt++) {
        const int kbase = kt * 64;
        // ---- cooperative K/V tile load + split + (V) transpose ----
        {
            const float* kp = Kg + (((size_t)(b * SS + kbase + lr)) * NKV + kvh) * HD + lcg;
            const float* vp = Vg + (((size_t)(b * SS + kbase + lr)) * NKV + kvh) * HD + lcg;
#pragma unroll
            for (int dd = 0; dd < 32; dd += 4) {
                float4 kv = *(const float4*)(kp + dd);
                float kvv[4] = {kv.x, kv.y, kv.z, kv.w};
                uint32_t* dsth = (uint32_t*)&sKh[lr * FTS + lcg + dd];
                uint32_t* dstl = (uint32_t*)&sKl[lr * FTS + lcg + dd];
                dsth[0] = pack_bf16hi(kvv[0], kvv[1]);
                dsth[1] = pack_bf16hi(kvv[2], kvv[3]);
                dstl[0] = pack_bf16lo(kvv[0], kvv[1]);
                dstl[1] = pack_bf16lo(kvv[2], kvv[3]);

                float4 vv = *(const float4*)(vp + dd);
                float vvv[4] = {vv.x, vv.y, vv.z, vv.w};
#pragma unroll
                for (int j = 0; j < 4; j++) {
                    __nv_bfloat16 hv = __float2bfloat16_rn(vvv[j]);
                    __nv_bfloat16 lv = __float2bfloat16_rn(vvv[j] - __bfloat162float(hv));
                    sVh[(lcg + dd + j) * FTS + lr] = hv;
                    sVl[(lcg + dd + j) * FTS + lr] = lv;
                }
            }
        }
        __syncthreads();

        // ---- S = Q K^T (3-term split) ----
        float s[8][4];
#pragma unroll
        for (int ni = 0; ni < 8; ni++)
#pragma unroll
            for (int j = 0; j < 4; j++) s[ni][j] = 0.0f;

#pragma unroll
        for (int kk = 0; kk < 4; kk++) {
#pragma unroll
            for (int ni = 0; ni < 8; ni++) {
                const __nv_bfloat16* ph = sKh + (ni * 8 + g) * FTS + kk * 16 + 2 * t;
                const __nv_bfloat16* pl = sKl + (ni * 8 + g) * FTS + kk * 16 + 2 * t;
                uint32_t bh0 = *(const uint32_t*)ph;
                uint32_t bh1 = *(const uint32_t*)(ph + 8);
                uint32_t bl0 = *(const uint32_t*)pl;
                uint32_t bl1 = *(const uint32_t*)(pl + 8);
                MMA16816(s[ni], qh[kk], bh0, bh1);
                MMA16816(s[ni], qh[kk], bl0, bl1);
                MMA16816(s[ni], ql[kk], bh0, bh1);
            }
        }

        // ---- causal mask (last tile only) ----
        if (kt == ntiles - 1) {
#pragma unroll
            for (int ni = 0; ni < 8; ni++) {
#pragma unroll
                for (int j = 0; j < 4; j++) {
                    int key = kbase + ni * 8 + 2 * t + (j & 1);
                    int row = rbase + g + (j >> 1) * 8;
                    if (key > row) s[ni][j] = -1e30f;
                }
            }
        }

        // ---- online softmax ----
        float tm0 = -1e30f, tm1 = -1e30f;
#pragma unroll
        for (int ni = 0; ni < 8; ni++) {
            tm0 = fmaxf(tm0, fmaxf(s[ni][0], s[ni][1]));
            tm1 = fmaxf(tm1, fmaxf(s[ni][2], s[ni][3]));
        }
        tm0 = fmaxf(tm0, __shfl_xor_sync(0xFFFFFFFF, tm0, 1));
        tm0 = fmaxf(tm0, __shfl_xor_sync(0xFFFFFFFF, tm0, 2));
        tm1 = fmaxf(tm1, __shfl_xor_sync(0xFFFFFFFF, tm1, 1));
        tm1 = fmaxf(tm1, __shfl_xor_sync(0xFFFFFFFF, tm1, 2));

        float mn0 = fmaxf(m0, tm0), mn1 = fmaxf(m1, tm1);
        float c0 = expf_fast(m0 - mn0), c1 = expf_fast(m1 - mn1);
        l0 *= c0; l1 *= c1;
#pragma unroll
        for (int ni = 0; ni < 8; ni++) {
            o[ni][0] *= c0; o[ni][1] *= c0;
            o[ni][2] *= c1; o[ni][3] *= c1;
        }
        float rs0 = 0.0f, rs1 = 0.0f;
#pragma unroll
        for (int ni = 0; ni < 8; ni++) {
            s[ni][0] = expf_fast(s[ni][0] - mn0);
            s[ni][1] = expf_fast(s[ni][1] - mn0);
            s[ni][2] = expf_fast(s[ni][2] - mn1);
            s[ni][3] = expf_fast(s[ni][3] - mn1);
            rs0 += s[ni][0] + s[ni][1];
            rs1 += s[ni][2] + s[ni][3];
        }
        rs0 += __shfl_xor_sync(0xFFFFFFFF, rs0, 1);
        rs0 += __shfl_xor_sync(0xFFFFFFFF, rs0, 2);
        rs1 += __shfl_xor_sync(0xFFFFFFFF, rs1, 1);
        rs1 += __shfl_xor_sync(0xFFFFFFFF, rs1, 2);
        l0 += rs0; l1 += rs1;
        m0 = mn0; m1 = mn1;

        // ---- O += P V (3-term split; P frags straight from S c-frags) ----
#pragma unroll
        for (int kk = 0; kk < 4; kk++) {
            const float* s0 = s[2 * kk];
            const float* s1 = s[2 * kk + 1];
            uint32_t ah[4], al[4];
            ah[0] = pack_bf16hi(s0[0], s0[1]);  al[0] = pack_bf16lo(s0[0], s0[1]);
            ah[1] = pack_bf16hi(s0[2], s0[3]);  al[1] = pack_bf16lo(s0[2], s0[3]);
            ah[2] = pack_bf16hi(s1[0], s1[1]);  al[2] = pack_bf16lo(s1[0], s1[1]);
            ah[3] = pack_bf16hi(s1[2], s1[3]);  al[3] = pack_bf16lo(s1[2], s1[3]);
#pragma unroll
            for (int ni = 0; ni < 8; ni++) {
                const __nv_bfloat16* pvh = sVh + (ni * 8 + g) * FTS + kk * 16 + 2 * t;
                const __nv_bfloat16* pvl = sVl + (ni * 8 + g) * FTS + kk * 16 + 2 * t;
                uint32_t vh0 = *(const uint32_t*)pvh;
                uint32_t vh1 = *(const uint32_t*)(pvh + 8);
                uint32_t vl0 = *(const uint32_t*)pvl;
                uint32_t vl1 = *(const uint32_t*)(pvl + 8);
                MMA16816(o[ni], ah, vh0, vh1);
                MMA16816(o[ni], al, vh0, vh1);
                MMA16816(o[ni], ah, vl0, vl1);
            }
        }
        __syncthreads();
    }

    // ---- epilogue ----
    float i0 = 1.0f / l0, i1 = 1.0f / l1;
#pragma unroll
    for (int ni = 0; ni < 8; ni++) {
        float* op0 = O + (((size_t)(b * SS + rbase + g)) * NH + h) * HD + ni * 8 + 2 * t;
        float* op1 = O + (((size_t)(b * SS + rbase + g + 8)) * NH + h) * HD + ni * 8 + 2 * t;
        *(float2*)op0 = make_float2(o[ni][0] * i0, o[ni][1] * i0);
        *(float2*)op1 = make_float2(o[ni][2] * i1, o[ni][3] * i1);
    }
}

// ---------------- launch -----------------------------------------------------
extern "C" void kernel_launch(void* const* d_in, const int* in_sizes, int n_in,
                              void* d_out, int out_size)
{
    (void)in_sizes; (void)n_in; (void)out_size;
    const float* X  = (const float*)d_in[0];
    const float* Wq = (const float*)d_in[1];
    const float* Wk = (const float*)d_in[2];
    const float* Wv = (const float*)d_in[3];
    const float* Wo = (const float*)d_in[4];

    float *q, *k, *v, *attn;
    __nv_bfloat16 *Xx, *attnx, *Wqx, *Wkx, *Wvx, *Wox;
    cudaGetSymbolAddress((void**)&q,     g_q);
    cudaGetSymbolAddress((void**)&k,     g_k);
    cudaGetSymbolAddress((void**)&v,     g_v);
    cudaGetSymbolAddress((void**)&attn,  g_attn);
    cudaGetSymbolAddress((void**)&Xx,    g_Xx);
    cudaGetSymbolAddress((void**)&attnx, g_attnx);
    cudaGetSymbolAddress((void**)&Wqx,   g_Wqx);
    cudaGetSymbolAddress((void**)&Wkx,   g_Wkx);
    cudaGetSymbolAddress((void**)&Wvx,   g_Wvx);
    cudaGetSymbolAddress((void**)&Wox,   g_Wox);

    const int M = BB * SS;        // 4096

    invf_kernel<<<1, 32>>>();

    expandA_kernel<<<(M * (DD / 4) + 255) / 256, 256>>>(X, Xx, M, DD);
    expandBt_kernel<<<((NH * HD) * (DD / 4) + 255) / 256, 256>>>(Wq, Wqx, DD, NH * HD);
    expandBt_kernel<<<((NKV * HD) * (DD / 4) + 255) / 256, 256>>>(Wk, Wkx, DD, NKV * HD);
    expandBt_kernel<<<((NKV * HD) * (DD / 4) + 255) / 256, 256>>>(Wv, Wvx, DD, NKV * HD);
    expandBt_kernel<<<(DD * (DD / 4) + 255) / 256, 256>>>(Wo, Wox, DD, DD);

    gemm_bf16_kernel<<<dim3((NH * HD) / 128,  M / 128), 256>>>(M, NH * HD,  Xx, Wqx, q);
    gemm_bf16_kernel<<<dim3((NKV * HD) / 128, M / 128), 256>>>(M, NKV * HD, Xx, Wkx, k);
    gemm_bf16_kernel<<<dim3((NKV * HD) / 128, M / 128), 256>>>(M, NKV * HD, Xx, Wvx, v);

    int nrope = M * (NH + NKV) * (HD / 2);
    rope_kernel<<<(nrope + 255) / 256, 256>>>(q, k, nrope);

    // tensor-core causal GQA flash attention
    flash_mma_kernel<<<dim3(SS / 64, NH, BB), 128>>>(q, k, v, attn);

    expandA_kernel<<<(M * (DD / 4) + 255) / 256, 256>>>(attn, attnx, M, DD);
    gemm_bf16_kernel<<<dim3(DD / 128, M / 128), 256>>>(M, DD, attnx, Wox, (float*)d_out);
}